// round 1
// baseline (speedup 1.0000x reference)
#include <cuda_runtime.h>

// DepthConv: out[b,o,h,w] = sum_{c,i,j} w[o,c,i,j] * x[b,c,h+i-1,w+j-1]
//                            * exp(-ALPHA*|depth[b,h,w] - depth[b,h+i-1,w+j-1]|)
// Gate is independent of c and o -> fold gate into the x operand per tap and
// accumulate 9 shifted GEMMs (M=64 o, N=pixels, K=512) into ONE accumulator.

#define ALPHA_F 8.3f

constexpr int Bn = 8;
constexpr int Cn = 512;
constexpr int Hn = 64;
constexpr int Wn = 64;
constexpr int On = 64;

constexpr int TH = 4;            // tile rows
constexpr int TW = 16;           // tile cols
constexpr int NPIX = TH * TW;    // 64 pixels per block
constexpr int CC = 16;           // c-chunk

// Pre-transposed weights: [tap][c][o], o contiguous (coalesced staging loads).
__device__ float g_wt[9 * Cn * On];

__global__ void transpose_w_kernel(const float* __restrict__ w) {
    int idx = blockIdx.x * blockDim.x + threadIdx.x;
    if (idx >= On * Cn * 9) return;
    // w layout: [o][c][3][3] -> idx = (o*Cn + c)*9 + t
    int t = idx % 9;
    int c = (idx / 9) % Cn;
    int o = idx / (9 * Cn);
    g_wt[(t * Cn + c) * On + o] = w[idx];
}

__global__ __launch_bounds__(256) void depthconv_kernel(
    const float* __restrict__ x,
    const float* __restrict__ depth,
    float* __restrict__ out)
{
    __shared__ float g_s[9][NPIX];      // gates per tap per pixel
    __shared__ float xg_s[CC][NPIX];    // gated, shifted x chunk
    __shared__ float w_s[CC][On];       // weight chunk

    const int blk  = blockIdx.x;
    const int b    = blk >> 6;          // / 64 tiles per image
    const int tile = blk & 63;
    const int h0   = (tile >> 2) * TH;  // 16 tile-rows
    const int w0   = (tile & 3) * TW;   // 4 tile-cols

    const int tid = threadIdx.x;

    // ---- Precompute gates: 9 taps x 64 pixels ----
    if (tid < NPIX) {
        const int p  = tid;
        const int hh = h0 + (p >> 4);
        const int ww = w0 + (p & 15);
        const float* dptr = depth + b * Hn * Wn;
        const float d0 = dptr[hh * Wn + ww];
        #pragma unroll
        for (int t = 0; t < 9; t++) {
            const int di = t / 3 - 1, dj = t % 3 - 1;
            const int h2 = hh + di, w2 = ww + dj;
            float g = 0.f;
            if (h2 >= 0 && h2 < Hn && w2 >= 0 && w2 < Wn)
                g = __expf(-ALPHA_F * fabsf(d0 - dptr[h2 * Wn + w2]));
            g_s[t][p] = g;
        }
    }
    __syncthreads();

    float acc[16];
    #pragma unroll
    for (int i = 0; i < 16; i++) acc[i] = 0.f;

    const int og = (tid >> 4) * 4;      // o microtile base   (0..60)
    const int pg = (tid & 15) * 4;      // pixel microtile base (0..60)

    const float* xb = x + (size_t)b * Cn * Hn * Wn;

    float xr[4], wr[4];                 // pipeline registers

    auto load = [&](int t, int c0) {
        const int di = t / 3 - 1, dj = t % 3 - 1;
        const float* wt = &g_wt[(t * Cn + c0) * On];
        #pragma unroll
        for (int k = 0; k < 4; k++) {
            const int e  = tid + k * 256;       // 0..1023
            const int cl = e >> 6;              // c within chunk
            const int p  = e & 63;              // pixel
            const int hh = h0 + (p >> 4) + di;
            const int ww = w0 + (p & 15) + dj;
            float v = 0.f;
            if (hh >= 0 && hh < Hn && ww >= 0 && ww < Wn)
                v = xb[(size_t)(c0 + cl) * Hn * Wn + hh * Wn + ww];
            xr[k] = v * g_s[t][p];
            wr[k] = wt[e];                      // contiguous: cl*64 + o
        }
    };

    load(0, 0);

    for (int t = 0; t < 9; t++) {
        for (int c0 = 0; c0 < Cn; c0 += CC) {
            __syncthreads();
            // commit staged chunk to smem
            #pragma unroll
            for (int k = 0; k < 4; k++) {
                const int e = tid + k * 256;
                xg_s[e >> 6][e & 63] = xr[k];
                w_s[e >> 6][e & 63]  = wr[k];
            }
            __syncthreads();

            // prefetch next chunk (globals overlap with compute below)
            {
                int nt = t, nc = c0 + CC;
                if (nc == Cn) { nt = t + 1; nc = 0; }
                if (nt < 9) load(nt, nc);
            }

            // compute: 16 c-steps x (4 o x 4 pix) FMAs
            #pragma unroll
            for (int c = 0; c < CC; c++) {
                const float4 wv = *reinterpret_cast<const float4*>(&w_s[c][og]);
                const float4 xv = *reinterpret_cast<const float4*>(&xg_s[c][pg]);
                acc[0]  += wv.x * xv.x;  acc[1]  += wv.x * xv.y;
                acc[2]  += wv.x * xv.z;  acc[3]  += wv.x * xv.w;
                acc[4]  += wv.y * xv.x;  acc[5]  += wv.y * xv.y;
                acc[6]  += wv.y * xv.z;  acc[7]  += wv.y * xv.w;
                acc[8]  += wv.z * xv.x;  acc[9]  += wv.z * xv.y;
                acc[10] += wv.z * xv.z;  acc[11] += wv.z * xv.w;
                acc[12] += wv.w * xv.x;  acc[13] += wv.w * xv.y;
                acc[14] += wv.w * xv.z;  acc[15] += wv.w * xv.w;
            }
        }
    }

    // ---- Epilogue ----
    float* ob = out + (size_t)b * On * Hn * Wn;
    #pragma unroll
    for (int i = 0; i < 4; i++) {
        #pragma unroll
        for (int j = 0; j < 4; j++) {
            const int p  = pg + j;
            const int hh = h0 + (p >> 4);
            const int ww = w0 + (p & 15);
            ob[(size_t)(og + i) * Hn * Wn + hh * Wn + ww] = acc[i * 4 + j];
        }
    }
}

extern "C" void kernel_launch(void* const* d_in, const int* in_sizes, int n_in,
                              void* d_out, int out_size) {
    const float* x     = (const float*)d_in[0];   // (8,512,64,64)
    const float* depth = (const float*)d_in[1];   // (8,1,64,64)
    const float* w     = (const float*)d_in[2];   // (64,512,3,3)
    float* out = (float*)d_out;                   // (8,64,64,64)

    {
        const int n = On * Cn * 9;
        transpose_w_kernel<<<(n + 255) / 256, 256>>>(w);
    }
    depthconv_kernel<<<Bn * 64, 256>>>(x, depth, out);
}

// round 3
// speedup vs baseline: 2.6236x; 2.6236x over previous
#include <cuda_runtime.h>
#include <cuda_fp16.h>
#include <cstdint>

// DepthConv as 9 gated shifted GEMMs on the tensor pipe (legacy mma.sync,
// baseline PTX -> works through the compute_103 PTX stage).
// out[b,o,p] = sum_{t,c} w[t,o,c] * (x[b,c,p+shift(t)] * gate[b,t,p])
// Per CTA: 128 pixels (M) x 64 outputs (N), K = 9*512 = 4608 accumulated in
// registers via mma.sync.m16n8k16 f16->f32.

#define ALPHA_F 8.3f

constexpr int Bn = 8;
constexpr int Cn = 512;
constexpr int Hn = 64;
constexpr int Wn = 64;
constexpr int On = 64;
constexpr int PIXn = Hn * Wn;       // 4096

constexpr int Mt = 128;             // pixels per CTA (8 rows x 16 cols)
constexpr int KC = 64;              // c-chunk
constexpr int NITER = 9 * (Cn / KC);  // 72
constexpr int AST = 72;             // smem row stride in halves (64 + 8 pad)

// ---- device-global scratch ----
__device__ float  g_xT[(size_t)Bn * PIXn * Cn];   // [b][pixel][c] fp32
__device__ __half g_wh[9 * On * Cn];              // [tap][o][c]  fp16

// ---- smem layout (bytes) ----
constexpr int ABUF = Mt * AST * 2;          // 18432
constexpr int BBUF = On * AST * 2;          // 9216
constexpr int OFF_A = 0;                    // 2 buffers
constexpr int OFF_B = 2 * ABUF;             // 36864
constexpr int OFF_G = OFF_B + 2 * BBUF;     // 55296 (gates 9*128 fp32)
constexpr int SMEM_TOTAL = OFF_G + 9 * Mt * 4;   // 59904

// ====================== helpers ======================
__device__ __forceinline__ uint32_t smem_u32(const void* p) {
    uint32_t a;
    asm("{ .reg .u64 t; cvta.to.shared.u64 t, %1; cvt.u32.u64 %0, t; }"
        : "=r"(a) : "l"(p));
    return a;
}
__device__ __forceinline__ void ldsm_x4(uint32_t* r, uint32_t addr) {
    asm volatile("ldmatrix.sync.aligned.m8n8.x4.shared.b16 {%0,%1,%2,%3}, [%4];"
        : "=r"(r[0]), "=r"(r[1]), "=r"(r[2]), "=r"(r[3]) : "r"(addr));
}
__device__ __forceinline__ void mma16816(float* c, const uint32_t* a,
                                         uint32_t b0, uint32_t b1) {
    asm volatile(
        "mma.sync.aligned.m16n8k16.row.col.f32.f16.f16.f32 "
        "{%0,%1,%2,%3}, {%4,%5,%6,%7}, {%8,%9}, {%0,%1,%2,%3};"
        : "+f"(c[0]), "+f"(c[1]), "+f"(c[2]), "+f"(c[3])
        : "r"(a[0]), "r"(a[1]), "r"(a[2]), "r"(a[3]), "r"(b0), "r"(b1));
}

// ====================== pre-pass kernels ======================
// x[b][c][p] -> g_xT[b][p][c] (fp32, tiled 32x32 transpose)
__global__ __launch_bounds__(256) void transpose_x(const float* __restrict__ x) {
    __shared__ float tile[32][33];
    const int b  = blockIdx.z;
    const int c0 = blockIdx.y * 32;
    const int p0 = blockIdx.x * 32;
    const int tx = threadIdx.x & 31;
    const int ty = threadIdx.x >> 5;   // 0..7
    #pragma unroll
    for (int j = 0; j < 4; j++)
        tile[ty + 8 * j][tx] = x[((size_t)(b * Cn + c0 + ty + 8 * j)) * PIXn + p0 + tx];
    __syncthreads();
    #pragma unroll
    for (int j = 0; j < 4; j++)
        g_xT[((size_t)(b * PIXn + p0 + ty + 8 * j)) * Cn + c0 + tx] = tile[tx][ty + 8 * j];
}

// w[o][c][3][3] -> g_wh[t][o][c] fp16 (single rounding of B operand)
__global__ void prep_w(const float* __restrict__ w) {
    int idx = blockIdx.x * blockDim.x + threadIdx.x;   // [t][o][c]
    if (idx >= 9 * On * Cn) return;
    int c = idx % Cn;
    int o = (idx / Cn) % On;
    int t = idx / (Cn * On);
    g_wh[idx] = __float2half_rn(w[((size_t)o * Cn + c) * 9 + t]);
}

// ====================== main kernel ======================
__global__ __launch_bounds__(256) void depthconv_mma(
    const float* __restrict__ depth,
    float* __restrict__ out)
{
    extern __shared__ __align__(16) char smem[];
    __half* As  = reinterpret_cast<__half*>(smem + OFF_A);   // [2][128][72]
    __half* Bs  = reinterpret_cast<__half*>(smem + OFF_B);   // [2][64][72]
    float*  g_s = reinterpret_cast<float*>(smem + OFF_G);    // [9][128]

    const int tid = threadIdx.x;
    const int wid = tid >> 5;
    const int lid = tid & 31;

    const int blk = blockIdx.x;          // 0..255
    const int b   = blk >> 5;
    const int tl  = blk & 31;
    const int h0  = (tl >> 2) * 8;       // 8 pixel rows
    const int w0  = (tl & 3) * 16;       // 16 pixel cols

    // ---- gates: 9 taps x 128 pixels ----
    if (tid < Mt) {
        const int hh = h0 + (tid >> 4);
        const int ww = w0 + (tid & 15);
        const float* dptr = depth + b * PIXn;
        const float d0 = dptr[hh * Wn + ww];
        #pragma unroll
        for (int t = 0; t < 9; t++) {
            const int h2 = hh + t / 3 - 1, w2 = ww + t % 3 - 1;
            float g = 0.f;
            if (h2 >= 0 && h2 < Hn && w2 >= 0 && w2 < Wn)
                g = __expf(-ALPHA_F * fabsf(d0 - dptr[h2 * Wn + w2]));
            g_s[t * Mt + tid] = g;
        }
    }
    __syncthreads();

    const float* xb = g_xT + (size_t)b * PIXn * Cn;

    // ---- staging thread mapping ----
    const int sm_ = tid >> 1;            // pixel 0..127 (2 threads/pixel)
    const int sc_ = (tid & 1) * 32;      // c half
    const int bo_ = tid >> 2;            // o 0..63 (4 threads/o)
    const int bc_ = (tid & 3) * 8;       // 8-half segment

    // ---- warp tiling: 4 (m) x 2 (n) warps; warp tile 32x32 ----
    const int wm = (wid & 3) * 32;
    const int wn = (wid >> 2) * 32;

    float acc[2][4][4];
    #pragma unroll
    for (int i = 0; i < 2; i++)
        #pragma unroll
        for (int j = 0; j < 4; j++)
            #pragma unroll
            for (int k = 0; k < 4; k++) acc[i][j][k] = 0.f;

    float4 pa[8];
    uint4  pb0, pb1;

    auto prefetch = [&](int it) {
        const int t  = it >> 3;
        const int c0 = (it & 7) * KC;
        const int di = t / 3 - 1, dj = t % 3 - 1;
        const int hh = h0 + (sm_ >> 4) + di;
        const int ww = w0 + (sm_ & 15) + dj;
        int q = hh * Wn + ww;
        q = min(max(q, 0), PIXn - 1);    // gate is 0 out of bounds
        const float4* src = reinterpret_cast<const float4*>(
            xb + (size_t)q * Cn + c0 + sc_);
        #pragma unroll
        for (int i = 0; i < 8; i++) pa[i] = src[i];
        const uint4* wsrc = reinterpret_cast<const uint4*>(
            g_wh + ((size_t)t * On + bo_) * Cn + c0 + bc_);
        pb0 = wsrc[0];
        pb1 = wsrc[4];                   // +32 halves
    };

    auto commit = [&](int buf, int it) {
        const int t = it >> 3;
        const float g = g_s[t * Mt + sm_];
        __half* ad = As + buf * (Mt * AST) + sm_ * AST + sc_;
        #pragma unroll
        for (int i = 0; i < 8; i++) {
            __half2 h01 = __floats2half2_rn(pa[i].x * g, pa[i].y * g);
            __half2 h23 = __floats2half2_rn(pa[i].z * g, pa[i].w * g);
            uint2 u;
            u.x = *reinterpret_cast<uint32_t*>(&h01);
            u.y = *reinterpret_cast<uint32_t*>(&h23);
            *reinterpret_cast<uint2*>(ad + i * 4) = u;
        }
        __half* bd = Bs + buf * (On * AST) + bo_ * AST + bc_;
        *reinterpret_cast<uint4*>(bd)      = pb0;
        *reinterpret_cast<uint4*>(bd + 32) = pb1;
    };

    auto compute = [&](int buf) {
        const __half* ab = As + buf * (Mt * AST);
        const __half* bb = Bs + buf * (On * AST);
        #pragma unroll
        for (int ks = 0; ks < 4; ks++) {
            uint32_t af[2][4];
            #pragma unroll
            for (int mb = 0; mb < 2; mb++) {
                const int r = wm + mb * 16 + (lid & 15);
                const int c = ks * 16 + (lid >> 4) * 8;
                ldsm_x4(af[mb], smem_u32(ab + r * AST + c));
            }
            uint32_t bf[2][4];
            #pragma unroll
            for (int np = 0; np < 2; np++) {
                const int r = wn + np * 16 + (lid & 7) + ((lid >> 4) << 3);
                const int c = ks * 16 + (((lid >> 3) & 1) << 3);
                ldsm_x4(bf[np], smem_u32(bb + r * AST + c));
            }
            #pragma unroll
            for (int mb = 0; mb < 2; mb++)
                #pragma unroll
                for (int nb = 0; nb < 4; nb++)
                    mma16816(acc[mb][nb], af[mb],
                             bf[nb >> 1][(nb & 1) * 2],
                             bf[nb >> 1][(nb & 1) * 2 + 1]);
        }
    };

    prefetch(0);
    for (int it = 0; it < NITER; it++) {
        const int buf = it & 1;
        __syncthreads();                 // prior compute on this buf done
        commit(buf, it);
        if (it + 1 < NITER) prefetch(it + 1);
        __syncthreads();                 // staged data visible
        compute(buf);
    }

    // ---- epilogue: D(m=pixel, n=o) -> out[b][o][h][w] ----
    float* ob = out + (size_t)b * On * PIXn;
    const int mrow = wm + (lid >> 2);
    const int ncol = wn + (lid & 3) * 2;
    #pragma unroll
    for (int mb = 0; mb < 2; mb++) {
        #pragma unroll
        for (int half_ = 0; half_ < 2; half_++) {       // m, m+8
            const int m  = mrow + mb * 16 + half_ * 8;
            const int hh = h0 + (m >> 4);
            const int ww = w0 + (m & 15);
            const int pix = hh * Wn + ww;
            #pragma unroll
            for (int nb = 0; nb < 4; nb++) {
                const int o = ncol + nb * 8;
                ob[(size_t)o * PIXn + pix]       = acc[mb][nb][half_ * 2];
                ob[(size_t)(o + 1) * PIXn + pix] = acc[mb][nb][half_ * 2 + 1];
            }
        }
    }
}

// ====================== launch ======================
extern "C" void kernel_launch(void* const* d_in, const int* in_sizes, int n_in,
                              void* d_out, int out_size) {
    const float* x     = (const float*)d_in[0];   // (8,512,64,64)
    const float* depth = (const float*)d_in[1];   // (8,1,64,64)
    const float* w     = (const float*)d_in[2];   // (64,512,3,3)
    float* out = (float*)d_out;                   // (8,64,64,64)

    cudaFuncSetAttribute(depthconv_mma,
                         cudaFuncAttributeMaxDynamicSharedMemorySize,
                         SMEM_TOTAL);

    {
        dim3 g(PIXn / 32, Cn / 32, Bn);
        transpose_x<<<g, 256>>>(x);
    }
    {
        const int n = 9 * On * Cn;
        prep_w<<<(n + 255) / 256, 256>>>(w);
    }
    depthconv_mma<<<Bn * 32, 256, SMEM_TOTAL>>>(depth, out);
}

// round 4
// speedup vs baseline: 5.8484x; 2.2291x over previous
#include <cuda_runtime.h>
#include <cuda_fp16.h>
#include <cstdint>

// DepthConv: out[b,o,p] = sum_t gate[b,t,p] * sum_c w[t,o,c]*x[b,c,p+shift(t)]
// Taps computed as UNGATED fp16 GEMMs (mma.sync m16n8k16); gate applied by
// scaling accumulator registers per tap (distributive). A operand comes from a
// 10x18-pixel halo tile in smem via per-lane ldmatrix addressing (shift = +off).

#define ALPHA_F 8.3f

constexpr int Bn = 8;
constexpr int Cn = 512;
constexpr int Hn = 64;
constexpr int Wn = 64;
constexpr int On = 64;
constexpr int PIXn = Hn * Wn;       // 4096

constexpr int Mt = 128;             // pixels per CTA (8 rows x 16 cols)
constexpr int KC = 64;              // c-chunk
constexpr int HE = 180;             // halo entries (10 x 18)
constexpr int HS = 72;              // smem row stride in halves (64 + 8 pad)
constexpr int NITER = 9 * (Cn / KC);  // 72

// ---- device-global scratch ----
__device__ __half g_xh[(size_t)Bn * PIXn * Cn];   // [b][pixel][c] fp16
__device__ __half g_wh[9 * On * Cn];              // [tap][o][c]  fp16

// ---- smem layout (bytes) ----
constexpr int HBUF = HE * HS * 2;           // 25920
constexpr int BBUF = On * HS * 2;           // 9216
constexpr int OFF_H = 0;                    // 2 halo buffers
constexpr int OFF_B = 2 * HBUF;             // 51840
constexpr int OFF_G = OFF_B + 2 * BBUF;     // 70272 gates 9*128*4
constexpr int SMEM_TOTAL = OFF_G + 9 * Mt * 4;   // 74880

// ====================== helpers ======================
__device__ __forceinline__ uint32_t smem_u32(const void* p) {
    uint32_t a;
    asm("{ .reg .u64 t; cvta.to.shared.u64 t, %1; cvt.u32.u64 %0, t; }"
        : "=r"(a) : "l"(p));
    return a;
}
__device__ __forceinline__ void ldsm_x4(uint32_t* r, uint32_t addr) {
    asm volatile("ldmatrix.sync.aligned.m8n8.x4.shared.b16 {%0,%1,%2,%3}, [%4];"
        : "=r"(r[0]), "=r"(r[1]), "=r"(r[2]), "=r"(r[3]) : "r"(addr));
}
__device__ __forceinline__ void mma16816(float* c, const uint32_t* a,
                                         uint32_t b0, uint32_t b1) {
    asm volatile(
        "mma.sync.aligned.m16n8k16.row.col.f32.f16.f16.f32 "
        "{%0,%1,%2,%3}, {%4,%5,%6,%7}, {%8,%9}, {%0,%1,%2,%3};"
        : "+f"(c[0]), "+f"(c[1]), "+f"(c[2]), "+f"(c[3])
        : "r"(a[0]), "r"(a[1]), "r"(a[2]), "r"(a[3]), "r"(b0), "r"(b1));
}
#define CP_ASYNC16(dst, src) \
    asm volatile("cp.async.cg.shared.global [%0], [%1], 16;" \
                 :: "r"(dst), "l"(src) : "memory")
#define CP_COMMIT() asm volatile("cp.async.commit_group;" ::: "memory")
#define CP_WAIT1()  asm volatile("cp.async.wait_group 1;" ::: "memory")
#define CP_WAIT0()  asm volatile("cp.async.wait_group 0;" ::: "memory")

// ====================== pre-pass kernels ======================
// x[b][c][p] fp32 -> g_xh[b][p][c] fp16 (tiled transpose, single rounding)
__global__ __launch_bounds__(256) void transpose_x(const float* __restrict__ x) {
    __shared__ float tile[32][33];
    const int b  = blockIdx.z;
    const int c0 = blockIdx.y * 32;
    const int p0 = blockIdx.x * 32;
    const int tx = threadIdx.x & 31;
    const int ty = threadIdx.x >> 5;   // 0..7
    #pragma unroll
    for (int j = 0; j < 4; j++)
        tile[ty + 8 * j][tx] = x[((size_t)(b * Cn + c0 + ty + 8 * j)) * PIXn + p0 + tx];
    __syncthreads();
    #pragma unroll
    for (int j = 0; j < 4; j++)
        g_xh[((size_t)(b * PIXn + p0 + ty + 8 * j)) * Cn + c0 + tx] =
            __float2half_rn(tile[tx][ty + 8 * j]);
}

// w[o][c][3][3] -> g_wh[t][o][c] fp16
__global__ void prep_w(const float* __restrict__ w) {
    int idx = blockIdx.x * blockDim.x + threadIdx.x;   // [t][o][c]
    if (idx >= 9 * On * Cn) return;
    int c = idx % Cn;
    int o = (idx / Cn) % On;
    int t = idx / (Cn * On);
    g_wh[idx] = __float2half_rn(w[((size_t)o * Cn + c) * 9 + t]);
}

// ====================== main kernel ======================
__global__ __launch_bounds__(256, 2) void depthconv_mma(
    const float* __restrict__ depth,
    float* __restrict__ out)
{
    extern __shared__ __align__(16) char smem[];
    const uint32_t sb = smem_u32(smem);
    float* g_s = reinterpret_cast<float*>(smem + OFF_G);    // [9][128]

    const int tid = threadIdx.x;
    const int wid = tid >> 5;
    const int lid = tid & 31;

    const int blk = blockIdx.x;          // 0..255
    const int b   = blk >> 5;
    const int tl  = blk & 31;
    const int h0  = (tl >> 2) * 8;       // 8 pixel rows
    const int w0  = (tl & 3) * 16;       // 16 pixel cols

    // ---- gates: 9 taps x 128 pixels ----
    if (tid < Mt) {
        const int hh = h0 + (tid >> 4);
        const int ww = w0 + (tid & 15);
        const float* dptr = depth + b * PIXn;
        const float d0 = dptr[hh * Wn + ww];
        #pragma unroll
        for (int t = 0; t < 9; t++) {
            const int h2 = hh + t / 3 - 1, w2 = ww + t % 3 - 1;
            float g = 0.f;
            if (h2 >= 0 && h2 < Hn && w2 >= 0 && w2 < Wn)
                g = __expf(-ALPHA_F * fabsf(d0 - dptr[h2 * Wn + w2]));
            g_s[t * Mt + tid] = g;
        }
    }

    // ---- per-thread halo staging slots (iter-invariant addressing) ----
    // 180 entries x 8 (16B segs) = 1440 chunks; thread handles tid, tid+256, ...
    const __half* xb = g_xh + (size_t)b * PIXn * Cn;
    const int nj = (tid < 160) ? 6 : 5;
    int qoff[6];       // global half offset (add c0)
    uint32_t soff[6];  // smem byte offset within halo buffer
    #pragma unroll
    for (int j = 0; j < 6; j++) {
        const int i = tid + j * 256;
        const int ent = i >> 3, seg = i & 7;
        const int hr = ent / 18, hc = ent - hr * 18;
        const int hh = min(max(h0 - 1 + hr, 0), Hn - 1);
        const int ww = min(max(w0 - 1 + hc, 0), Wn - 1);
        qoff[j] = (hh * Wn + ww) * Cn + seg * 8;
        soff[j] = (uint32_t)(ent * HS + seg * 8) * 2;
    }
    // B staging slots: 64 entries x 8 segs = 512 chunks, 2 per thread
    uint32_t bsoff[2];
    int boff[2];
    #pragma unroll
    for (int j = 0; j < 2; j++) {
        const int i = tid + j * 256;
        const int o = i >> 3, seg = i & 7;
        boff[j]  = o * Cn + seg * 8;              // add t*On*Cn + c0
        bsoff[j] = (uint32_t)(o * HS + seg * 8) * 2;
    }

    auto stage = [&](int it, int buf) {
        const int t  = it >> 3;
        const int c0 = (it & 7) * KC;
        const uint32_t hd = sb + OFF_H + buf * HBUF;
        #pragma unroll
        for (int j = 0; j < 6; j++)
            if (j < nj)
                CP_ASYNC16(hd + soff[j], (const char*)(xb + qoff[j] + c0));
        const uint32_t bd = sb + OFF_B + buf * BBUF;
        const __half* wsrc = g_wh + (size_t)t * On * Cn + c0;
        #pragma unroll
        for (int j = 0; j < 2; j++)
            CP_ASYNC16(bd + bsoff[j], (const char*)(wsrc + boff[j]));
    };

    // ---- warp tiling: 4 (m) x 2 (n) warps; warp tile 32x32 ----
    const int wm = (wid & 3) * 32;
    const int wn = (wid >> 2) * 32;

    // per-lane ldmatrix A row addresses (halo entry of untapped pixel)
    uint32_t abase[2];
    #pragma unroll
    for (int mb = 0; mb < 2; mb++) {
        const int m   = wm + mb * 16 + (lid & 15);
        const int ent = (m >> 4) * 18 + (m & 15);   // tap 0 position; +off(t)
        abase[mb] = sb + OFF_H + (uint32_t)(ent * HS) * 2 + (uint32_t)(lid >> 4) * 16;
    }
    // B ldsm lane address (within B buffer)
    const int br = (lid & 7) + ((lid >> 4) << 3);
    const uint32_t bcol = (uint32_t)(((lid >> 3) & 1) << 3) * 2;

    float facc[2][4][4];
    #pragma unroll
    for (int i = 0; i < 2; i++)
        #pragma unroll
        for (int j = 0; j < 4; j++)
            #pragma unroll
            for (int k = 0; k < 4; k++) facc[i][j][k] = 0.f;

    float pacc[2][4][4];

    stage(0, 0);
    CP_COMMIT();
    __syncthreads();   // also covers gate writes

    for (int it = 0; it < NITER; it++) {
        const int t   = it >> 3;
        const int buf = it & 1;

        if ((it & 7) == 0) {
            #pragma unroll
            for (int i = 0; i < 2; i++)
                #pragma unroll
                for (int j = 0; j < 4; j++)
                    #pragma unroll
                    for (int k = 0; k < 4; k++) pacc[i][j][k] = 0.f;
        }

        if (it + 1 < NITER) {
            stage(it + 1, buf ^ 1);
            CP_COMMIT();
            CP_WAIT1();
        } else {
            CP_WAIT0();
        }
        __syncthreads();

        // ---- compute: 4 k-steps of 16 over this c-chunk ----
        const uint32_t aoff = (uint32_t)(((t / 3) * 18 + (t % 3)) * HS) * 2
                            + (uint32_t)buf * HBUF;
        const uint32_t bbuf = sb + OFF_B + buf * BBUF;
        #pragma unroll
        for (int ks = 0; ks < 4; ks++) {
            uint32_t af[2][4];
            #pragma unroll
            for (int mb = 0; mb < 2; mb++)
                ldsm_x4(af[mb], abase[mb] + aoff + ks * 32);
            uint32_t bf[2][4];
            #pragma unroll
            for (int np = 0; np < 2; np++)
                ldsm_x4(bf[np], bbuf + (uint32_t)((wn + np * 16 + br) * HS) * 2
                                + bcol + ks * 32);
            #pragma unroll
            for (int mb = 0; mb < 2; mb++)
                #pragma unroll
                for (int nb = 0; nb < 4; nb++)
                    mma16816(pacc[mb][nb], af[mb],
                             bf[nb >> 1][(nb & 1) * 2],
                             bf[nb >> 1][(nb & 1) * 2 + 1]);
        }

        // ---- end of tap: gate-scale partial into final ----
        if ((it & 7) == 7) {
            #pragma unroll
            for (int mb = 0; mb < 2; mb++) {
                const int r0 = wm + mb * 16 + (lid >> 2);
                const float g0 = g_s[t * Mt + r0];
                const float g1 = g_s[t * Mt + r0 + 8];
                #pragma unroll
                for (int nb = 0; nb < 4; nb++) {
                    facc[mb][nb][0] += g0 * pacc[mb][nb][0];
                    facc[mb][nb][1] += g0 * pacc[mb][nb][1];
                    facc[mb][nb][2] += g1 * pacc[mb][nb][2];
                    facc[mb][nb][3] += g1 * pacc[mb][nb][3];
                }
            }
        }
        __syncthreads();
    }

    // ---- epilogue: D(m=pixel, n=o) -> out[b][o][h][w] ----
    float* ob = out + (size_t)b * On * PIXn;
    const int mrow = wm + (lid >> 2);
    const int ncol = wn + (lid & 3) * 2;
    #pragma unroll
    for (int mb = 0; mb < 2; mb++) {
        #pragma unroll
        for (int half_ = 0; half_ < 2; half_++) {
            const int m  = mrow + mb * 16 + half_ * 8;
            const int hh = h0 + (m >> 4);
            const int ww = w0 + (m & 15);
            const int pix = hh * Wn + ww;
            #pragma unroll
            for (int nb = 0; nb < 4; nb++) {
                const int o = ncol + nb * 8;
                ob[(size_t)o * PIXn + pix]       = facc[mb][nb][half_ * 2];
                ob[(size_t)(o + 1) * PIXn + pix] = facc[mb][nb][half_ * 2 + 1];
            }
        }
    }
}

// ====================== launch ======================
extern "C" void kernel_launch(void* const* d_in, const int* in_sizes, int n_in,
                              void* d_out, int out_size) {
    const float* x     = (const float*)d_in[0];   // (8,512,64,64)
    const float* depth = (const float*)d_in[1];   // (8,1,64,64)
    const float* w     = (const float*)d_in[2];   // (64,512,3,3)
    float* out = (float*)d_out;                   // (8,64,64,64)

    cudaFuncSetAttribute(depthconv_mma,
                         cudaFuncAttributeMaxDynamicSharedMemorySize,
                         SMEM_TOTAL);

    {
        dim3 g(PIXn / 32, Cn / 32, Bn);
        transpose_x<<<g, 256>>>(x);
    }
    {
        const int n = 9 * On * Cn;
        prep_w<<<(n + 255) / 256, 256>>>(w);
    }
    depthconv_mma<<<Bn * 32, 256, SMEM_TOTAL>>>(depth, out);
}

// round 5
// speedup vs baseline: 6.5883x; 1.1265x over previous
#include <cuda_runtime.h>
#include <cuda_fp16.h>
#include <cstdint>

// DepthConv: out[b,o,p] = sum_t gate[b,t,p] * sum_c w[t,o,c]*x[b,c,p+shift(t)]
// Ungated fp16 GEMMs per tap (mma.sync m16n8k16), gate applied to accumulator
// registers per tap. A from a 10x18 pixel halo in smem (per-lane ldmatrix
// addressing, tap shift = constant byte offset). 3-stage cp.async pipeline.

#define ALPHA_F 8.3f

constexpr int Bn = 8;
constexpr int Cn = 512;
constexpr int Hn = 64;
constexpr int Wn = 64;
constexpr int On = 64;
constexpr int PIXn = Hn * Wn;       // 4096

constexpr int Mt = 128;             // pixels per CTA (8 rows x 16 cols)
constexpr int KC = 64;              // c-chunk
constexpr int HE = 180;             // halo entries (10 x 18)
constexpr int HS = 72;              // smem row stride in halves (64 + 8 pad)
constexpr int NITER = 9 * (Cn / KC);  // 72

// ---- device-global scratch ----
__device__ __half g_xh[(size_t)Bn * PIXn * Cn];   // [b][pixel][c] fp16
__device__ __half g_wh[9 * On * Cn];              // [tap][o][c]  fp16

// ---- smem layout (bytes): 3 pipeline stages ----
constexpr int HBUF = HE * HS * 2;           // 25920
constexpr int BBUF = On * HS * 2;           // 9216
constexpr int OFF_H = 0;                    // 3 halo buffers
constexpr int OFF_B = 3 * HBUF;             // 77760
constexpr int OFF_G = OFF_B + 3 * BBUF;     // 105408 gates 9*128*4
constexpr int SMEM_TOTAL = OFF_G + 9 * Mt * 4;   // 110016

// ====================== helpers ======================
__device__ __forceinline__ uint32_t smem_u32(const void* p) {
    uint32_t a;
    asm("{ .reg .u64 t; cvta.to.shared.u64 t, %1; cvt.u32.u64 %0, t; }"
        : "=r"(a) : "l"(p));
    return a;
}
__device__ __forceinline__ void ldsm_x4(uint32_t* r, uint32_t addr) {
    asm volatile("ldmatrix.sync.aligned.m8n8.x4.shared.b16 {%0,%1,%2,%3}, [%4];"
        : "=r"(r[0]), "=r"(r[1]), "=r"(r[2]), "=r"(r[3]) : "r"(addr));
}
__device__ __forceinline__ void mma16816(float* c, const uint32_t* a,
                                         uint32_t b0, uint32_t b1) {
    asm volatile(
        "mma.sync.aligned.m16n8k16.row.col.f32.f16.f16.f32 "
        "{%0,%1,%2,%3}, {%4,%5,%6,%7}, {%8,%9}, {%0,%1,%2,%3};"
        : "+f"(c[0]), "+f"(c[1]), "+f"(c[2]), "+f"(c[3])
        : "r"(a[0]), "r"(a[1]), "r"(a[2]), "r"(a[3]), "r"(b0), "r"(b1));
}
#define CP_ASYNC16(dst, src) \
    asm volatile("cp.async.cg.shared.global [%0], [%1], 16;" \
                 :: "r"(dst), "l"(src) : "memory")
#define CP_COMMIT() asm volatile("cp.async.commit_group;" ::: "memory")
#define CP_WAIT1()  asm volatile("cp.async.wait_group 1;" ::: "memory")
#define CP_WAIT0()  asm volatile("cp.async.wait_group 0;" ::: "memory")

// ====================== fused pre-pass ======================
// Part 1 (blocks [0, NT_BLK)): x[b][c][p] fp32 -> g_xh[b][p][c] fp16.
//   Tile: 64 channels x 32 pixels. Reads 128B rows, writes 128B half2 rows.
// Part 2 (blocks [NT_BLK, NT_BLK+NW_BLK)): w[o][c][3][3] -> g_wh[t][o][c].
constexpr int NT_BLK = (PIXn / 32) * (Cn / 64) * Bn;   // 8192
constexpr int NW_ELEM = 9 * On * Cn;                   // 294912
constexpr int NW_BLK = NW_ELEM / (256 * 8);            // 144

__global__ __launch_bounds__(256) void prep_all(const float* __restrict__ x,
                                                const float* __restrict__ w) {
    const int bi = blockIdx.x;
    if (bi < NT_BLK) {
        __shared__ float tile[64][33];
        const int b  = bi / ((PIXn / 32) * (Cn / 64));
        const int r  = bi % ((PIXn / 32) * (Cn / 64));
        const int c0 = (r / (PIXn / 32)) * 64;
        const int p0 = (r % (PIXn / 32)) * 32;
        const int tx = threadIdx.x & 31;
        const int ty = threadIdx.x >> 5;   // 0..7
        #pragma unroll
        for (int j = 0; j < 8; j++)
            tile[ty + 8 * j][tx] =
                x[((size_t)(b * Cn + c0 + ty + 8 * j)) * PIXn + p0 + tx];
        __syncthreads();
        // warp handles 4 pixel rows; lanes cover 32 half2 (64 channels)
        #pragma unroll
        for (int j = 0; j < 4; j++) {
            const int p = ty * 4 + j;
            __half2 v = __floats2half2_rn(tile[tx * 2][p], tile[tx * 2 + 1][p]);
            *reinterpret_cast<__half2*>(
                &g_xh[((size_t)(b * PIXn + p0 + p)) * Cn + c0 + tx * 2]) = v;
        }
    } else {
        const int base = (bi - NT_BLK) * 2048 + threadIdx.x;
        #pragma unroll
        for (int j = 0; j < 8; j++) {
            const int idx = base + j * 256;          // [t][o][c]
            const int c = idx % Cn;
            const int o = (idx / Cn) % On;
            const int t = idx / (Cn * On);
            g_wh[idx] = __float2half_rn(w[((size_t)o * Cn + c) * 9 + t]);
        }
    }
}

// ====================== main kernel ======================
__global__ __launch_bounds__(256, 2) void depthconv_mma(
    const float* __restrict__ depth,
    float* __restrict__ out)
{
    extern __shared__ __align__(16) char smem[];
    const uint32_t sb = smem_u32(smem);
    float* g_s = reinterpret_cast<float*>(smem + OFF_G);    // [9][128]

    const int tid = threadIdx.x;
    const int wid = tid >> 5;
    const int lid = tid & 31;

    const int blk = blockIdx.x;          // 0..255
    const int b   = blk >> 5;
    const int tl  = blk & 31;
    const int h0  = (tl >> 2) * 8;       // 8 pixel rows
    const int w0  = (tl & 3) * 16;       // 16 pixel cols

    // ---- gates: 9 taps x 128 pixels ----
    if (tid < Mt) {
        const int hh = h0 + (tid >> 4);
        const int ww = w0 + (tid & 15);
        const float* dptr = depth + b * PIXn;
        const float d0 = dptr[hh * Wn + ww];
        #pragma unroll
        for (int t = 0; t < 9; t++) {
            const int h2 = hh + t / 3 - 1, w2 = ww + t % 3 - 1;
            float g = 0.f;
            if (h2 >= 0 && h2 < Hn && w2 >= 0 && w2 < Wn)
                g = __expf(-ALPHA_F * fabsf(d0 - dptr[h2 * Wn + w2]));
            g_s[t * Mt + tid] = g;
        }
    }

    // ---- per-thread halo staging slots (iter-invariant addressing) ----
    const __half* xb = g_xh + (size_t)b * PIXn * Cn;
    const int nj = (tid < 160) ? 6 : 5;
    int qoff[6];       // global half offset (add c0)
    uint32_t soff[6];  // smem byte offset within halo buffer
    #pragma unroll
    for (int j = 0; j < 6; j++) {
        const int i = tid + j * 256;
        const int ent = i >> 3, seg = i & 7;
        const int hr = ent / 18, hc = ent - hr * 18;
        const int hh = min(max(h0 - 1 + hr, 0), Hn - 1);
        const int ww = min(max(w0 - 1 + hc, 0), Wn - 1);
        qoff[j] = (hh * Wn + ww) * Cn + seg * 8;
        soff[j] = (uint32_t)(ent * HS + seg * 8) * 2;
    }
    uint32_t bsoff[2];
    int boff[2];
    #pragma unroll
    for (int j = 0; j < 2; j++) {
        const int i = tid + j * 256;
        const int o = i >> 3, seg = i & 7;
        boff[j]  = o * Cn + seg * 8;
        bsoff[j] = (uint32_t)(o * HS + seg * 8) * 2;
    }

    auto stage = [&](int it, int buf) {
        const int t  = it >> 3;
        const int c0 = (it & 7) * KC;
        const uint32_t hd = sb + OFF_H + buf * HBUF;
        #pragma unroll
        for (int j = 0; j < 6; j++)
            if (j < nj)
                CP_ASYNC16(hd + soff[j], (const char*)(xb + qoff[j] + c0));
        const uint32_t bd = sb + OFF_B + buf * BBUF;
        const __half* wsrc = g_wh + (size_t)t * On * Cn + c0;
        #pragma unroll
        for (int j = 0; j < 2; j++)
            CP_ASYNC16(bd + bsoff[j], (const char*)(wsrc + boff[j]));
    };

    // ---- warp tiling: 4 (m) x 2 (n) warps; warp tile 32x32 ----
    const int wm = (wid & 3) * 32;
    const int wn = (wid >> 2) * 32;

    uint32_t abase[2];                    // per-lane A ldmatrix base (tap 0)
    #pragma unroll
    for (int mb = 0; mb < 2; mb++) {
        const int m   = wm + mb * 16 + (lid & 15);
        const int ent = (m >> 4) * 18 + (m & 15);
        abase[mb] = sb + OFF_H + (uint32_t)(ent * HS) * 2 + (uint32_t)(lid >> 4) * 16;
    }
    uint32_t bbase[2];                    // per-lane B ldmatrix base
    {
        const int br = (lid & 7) + ((lid >> 4) << 3);
        const uint32_t bcol = (uint32_t)(((lid >> 3) & 1) << 3) * 2;
        #pragma unroll
        for (int np = 0; np < 2; np++)
            bbase[np] = sb + OFF_B + (uint32_t)((wn + np * 16 + br) * HS) * 2 + bcol;
    }

    float facc[2][4][4];
    #pragma unroll
    for (int i = 0; i < 2; i++)
        #pragma unroll
        for (int j = 0; j < 4; j++)
            #pragma unroll
            for (int k = 0; k < 4; k++) facc[i][j][k] = 0.f;

    float pacc[2][4][4];

    stage(0, 0); CP_COMMIT();
    stage(1, 1); CP_COMMIT();

    for (int it = 0; it < NITER; it++) {
        const int t   = it >> 3;
        const int buf = it % 3;

        if ((it & 7) == 0) {
            #pragma unroll
            for (int i = 0; i < 2; i++)
                #pragma unroll
                for (int j = 0; j < 4; j++)
                    #pragma unroll
                    for (int k = 0; k < 4; k++) pacc[i][j][k] = 0.f;
        }

        if (it == NITER - 1) { CP_WAIT0(); } else { CP_WAIT1(); }
        __syncthreads();   // staged data (and, first iter, gates) visible

        // ---- compute: 4 k-steps of 16 over this c-chunk ----
        const uint32_t aoff = (uint32_t)(((t / 3) * 18 + (t % 3)) * HS) * 2
                            + (uint32_t)buf * HBUF;
        const uint32_t boffb = (uint32_t)buf * BBUF;
        #pragma unroll
        for (int ks = 0; ks < 4; ks++) {
            uint32_t af[2][4];
            #pragma unroll
            for (int mb = 0; mb < 2; mb++)
                ldsm_x4(af[mb], abase[mb] + aoff + ks * 32);
            uint32_t bf[2][4];
            #pragma unroll
            for (int np = 0; np < 2; np++)
                ldsm_x4(bf[np], bbase[np] + boffb + ks * 32);
            #pragma unroll
            for (int mb = 0; mb < 2; mb++)
                #pragma unroll
                for (int nb = 0; nb < 4; nb++)
                    mma16816(pacc[mb][nb], af[mb],
                             bf[nb >> 1][(nb & 1) * 2],
                             bf[nb >> 1][(nb & 1) * 2 + 1]);
        }

        // stage 2 ahead (3rd buffer removes WAR hazard; no end-of-loop sync)
        if (it + 2 < NITER) {
            stage(it + 2, (it + 2) % 3);
            CP_COMMIT();
        }

        // ---- end of tap: gate-scale partial into final ----
        if ((it & 7) == 7) {
            #pragma unroll
            for (int mb = 0; mb < 2; mb++) {
                const int r0 = wm + mb * 16 + (lid >> 2);
                const float g0 = g_s[t * Mt + r0];
                const float g1 = g_s[t * Mt + r0 + 8];
                #pragma unroll
                for (int nb = 0; nb < 4; nb++) {
                    facc[mb][nb][0] += g0 * pacc[mb][nb][0];
                    facc[mb][nb][1] += g0 * pacc[mb][nb][1];
                    facc[mb][nb][2] += g1 * pacc[mb][nb][2];
                    facc[mb][nb][3] += g1 * pacc[mb][nb][3];
                }
            }
        }
    }

    // ---- epilogue: D(m=pixel, n=o) -> out[b][o][h][w] ----
    float* ob = out + (size_t)b * On * PIXn;
    const int mrow = wm + (lid >> 2);
    const int ncol = wn + (lid & 3) * 2;
    #pragma unroll
    for (int mb = 0; mb < 2; mb++) {
        #pragma unroll
        for (int half_ = 0; half_ < 2; half_++) {
            const int m  = mrow + mb * 16 + half_ * 8;
            const int hh = h0 + (m >> 4);
            const int ww = w0 + (m & 15);
            const int pix = hh * Wn + ww;
            #pragma unroll
            for (int nb = 0; nb < 4; nb++) {
                const int o = ncol + nb * 8;
                ob[(size_t)o * PIXn + pix]       = facc[mb][nb][half_ * 2];
                ob[(size_t)(o + 1) * PIXn + pix] = facc[mb][nb][half_ * 2 + 1];
            }
        }
    }
}

// ====================== launch ======================
extern "C" void kernel_launch(void* const* d_in, const int* in_sizes, int n_in,
                              void* d_out, int out_size) {
    const float* x     = (const float*)d_in[0];   // (8,512,64,64)
    const float* depth = (const float*)d_in[1];   // (8,1,64,64)
    const float* w     = (const float*)d_in[2];   // (64,512,3,3)
    float* out = (float*)d_out;                   // (8,64,64,64)

    cudaFuncSetAttribute(depthconv_mma,
                         cudaFuncAttributeMaxDynamicSharedMemorySize,
                         SMEM_TOTAL);

    prep_all<<<NT_BLK + NW_BLK, 256>>>(x, w);
    depthconv_mma<<<Bn * 32, 256, SMEM_TOTAL>>>(depth, out);
}

// round 6
// speedup vs baseline: 7.3001x; 1.1081x over previous
#include <cuda_runtime.h>
#include <cuda_fp16.h>
#include <cstdint>

// DepthConv: out[b,o,p] = sum_t gate[b,t,p] * sum_c w[t,o,c]*x[b,c,p+shift(t)]
// c-chunk-major loop: per epoch stage halo(c-chunk) ONCE + all 9 taps' B,
// then 9 taps x 4 k-steps of mma. Gate applied to A fragments in fp16
// (per-row HMUL2), accumulating all taps into one fp32 accumulator set.

#define ALPHA_F 8.3f

constexpr int Bn = 8;
constexpr int Cn = 512;
constexpr int Hn = 64;
constexpr int Wn = 64;
constexpr int On = 64;
constexpr int PIXn = Hn * Wn;       // 4096

constexpr int Mt = 128;             // pixels per CTA (8 rows x 16 cols)
constexpr int KC = 64;              // c-chunk per epoch
constexpr int EPOCHS = Cn / KC;     // 8
constexpr int HE = 180;             // halo entries (10 x 18)
constexpr int HS = 72;              // smem row stride in halves (64 + 8 pad)
constexpr int BROWS = 9 * On;       // 576 B rows per epoch (all taps)

// ---- device-global scratch ----
__device__ __half g_xh[(size_t)Bn * PIXn * Cn];   // [b][pixel][c] fp16
__device__ __half g_wh[9 * On * Cn];              // [tap][o][c]  fp16

// ---- smem layout (bytes): 2 buffers each ----
constexpr int HBUF = HE * HS * 2;            // 25920
constexpr int BBUF = BROWS * HS * 2;         // 82944
constexpr int OFF_H = 0;                     // 2 halo buffers
constexpr int OFF_B = 2 * HBUF;              // 51840
constexpr int OFF_G = OFF_B + 2 * BBUF;      // 217728  gates 9*128*4 (half2)
constexpr int SMEM_TOTAL = OFF_G + 9 * Mt * 4;  // 222336

// ====================== helpers ======================
__device__ __forceinline__ uint32_t smem_u32(const void* p) {
    uint32_t a;
    asm("{ .reg .u64 t; cvta.to.shared.u64 t, %1; cvt.u32.u64 %0, t; }"
        : "=r"(a) : "l"(p));
    return a;
}
__device__ __forceinline__ void ldsm_x4(uint32_t* r, uint32_t addr) {
    asm volatile("ldmatrix.sync.aligned.m8n8.x4.shared.b16 {%0,%1,%2,%3}, [%4];"
        : "=r"(r[0]), "=r"(r[1]), "=r"(r[2]), "=r"(r[3]) : "r"(addr));
}
__device__ __forceinline__ void mma16816(float* c, const uint32_t* a,
                                         uint32_t b0, uint32_t b1) {
    asm volatile(
        "mma.sync.aligned.m16n8k16.row.col.f32.f16.f16.f32 "
        "{%0,%1,%2,%3}, {%4,%5,%6,%7}, {%8,%9}, {%0,%1,%2,%3};"
        : "+f"(c[0]), "+f"(c[1]), "+f"(c[2]), "+f"(c[3])
        : "r"(a[0]), "r"(a[1]), "r"(a[2]), "r"(a[3]), "r"(b0), "r"(b1));
}
__device__ __forceinline__ uint32_t hmul2u(uint32_t a, uint32_t g) {
    __half2 r = __hmul2(*reinterpret_cast<__half2*>(&a),
                        *reinterpret_cast<__half2*>(&g));
    return *reinterpret_cast<uint32_t*>(&r);
}
#define CP_ASYNC16(dst, src) \
    asm volatile("cp.async.cg.shared.global [%0], [%1], 16;" \
                 :: "r"(dst), "l"(src) : "memory")
#define CP_COMMIT() asm volatile("cp.async.commit_group;" ::: "memory")
#define CP_WAIT1()  asm volatile("cp.async.wait_group 1;" ::: "memory")
#define CP_WAIT0()  asm volatile("cp.async.wait_group 0;" ::: "memory")

// ====================== fused pre-pass ======================
constexpr int NT_BLK = (PIXn / 32) * (Cn / 64) * Bn;   // 8192
constexpr int NW_ELEM = 9 * On * Cn;                   // 294912
constexpr int NW_BLK = NW_ELEM / (256 * 8);            // 144

__global__ __launch_bounds__(256) void prep_all(const float* __restrict__ x,
                                                const float* __restrict__ w) {
    const int bi = blockIdx.x;
    if (bi < NT_BLK) {
        __shared__ float tile[64][33];
        const int b  = bi / ((PIXn / 32) * (Cn / 64));
        const int r  = bi % ((PIXn / 32) * (Cn / 64));
        const int c0 = (r / (PIXn / 32)) * 64;
        const int p0 = (r % (PIXn / 32)) * 32;
        const int tx = threadIdx.x & 31;
        const int ty = threadIdx.x >> 5;   // 0..7
        #pragma unroll
        for (int j = 0; j < 8; j++)
            tile[ty + 8 * j][tx] =
                x[((size_t)(b * Cn + c0 + ty + 8 * j)) * PIXn + p0 + tx];
        __syncthreads();
        #pragma unroll
        for (int j = 0; j < 4; j++) {
            const int p = ty * 4 + j;
            __half2 v = __floats2half2_rn(tile[tx * 2][p], tile[tx * 2 + 1][p]);
            *reinterpret_cast<__half2*>(
                &g_xh[((size_t)(b * PIXn + p0 + p)) * Cn + c0 + tx * 2]) = v;
        }
    } else {
        const int base = (bi - NT_BLK) * 2048 + threadIdx.x;
        #pragma unroll
        for (int j = 0; j < 8; j++) {
            const int idx = base + j * 256;          // [t][o][c]
            const int c = idx % Cn;
            const int o = (idx / Cn) % On;
            const int t = idx / (Cn * On);
            g_wh[idx] = __float2half_rn(w[((size_t)o * Cn + c) * 9 + t]);
        }
    }
}

// ====================== main kernel ======================
__global__ __launch_bounds__(256, 1) void depthconv_mma(
    const float* __restrict__ depth,
    float* __restrict__ out)
{
    extern __shared__ __align__(16) char smem[];
    const uint32_t sb = smem_u32(smem);
    uint32_t* g_sp = reinterpret_cast<uint32_t*>(smem + OFF_G);  // [9][128] half2

    const int tid = threadIdx.x;
    const int wid = tid >> 5;
    const int lid = tid & 31;

    const int blk = blockIdx.x;          // 0..255
    const int b   = blk >> 5;
    const int tl  = blk & 31;
    const int h0  = (tl >> 2) * 8;       // 8 pixel rows
    const int w0  = (tl & 3) * 16;       // 16 pixel cols

    // ---- gates: 9 taps x 128 pixels, stored as (g,g) half2 ----
    if (tid < Mt) {
        const int hh = h0 + (tid >> 4);
        const int ww = w0 + (tid & 15);
        const float* dptr = depth + b * PIXn;
        const float d0 = dptr[hh * Wn + ww];
        #pragma unroll
        for (int t = 0; t < 9; t++) {
            const int h2 = hh + t / 3 - 1, w2 = ww + t % 3 - 1;
            float g = 0.f;
            if (h2 >= 0 && h2 < Hn && w2 >= 0 && w2 < Wn)
                g = __expf(-ALPHA_F * fabsf(d0 - dptr[h2 * Wn + w2]));
            const __half gh = __float2half_rn(g);
            __half2 gp = __halves2half2(gh, gh);
            g_sp[t * Mt + tid] = *reinterpret_cast<uint32_t*>(&gp);
        }
    }

    // ---- halo staging slots (epoch-invariant addressing) ----
    const __half* xb = g_xh + (size_t)b * PIXn * Cn;
    const int nj = (tid < 160) ? 6 : 5;   // 1440 chunks over 256 threads
    int qoff[6];        // global half offset (add c0)
    uint32_t soff[6];   // smem byte offset within halo buffer
    #pragma unroll
    for (int j = 0; j < 6; j++) {
        const int i = tid + j * 256;
        const int ent = i >> 3, seg = i & 7;
        const int hr = ent / 18, hc = ent - hr * 18;
        const int hh = min(max(h0 - 1 + hr, 0), Hn - 1);
        const int ww = min(max(w0 - 1 + hc, 0), Wn - 1);
        qoff[j] = (hh * Wn + ww) * Cn + seg * 8;
        soff[j] = (uint32_t)(ent * HS + seg * 8) * 2;
    }

    auto stage = [&](int e, int buf) {
        const int c0 = e * KC;
        const uint32_t hd = sb + OFF_H + buf * HBUF;
        #pragma unroll
        for (int j = 0; j < 6; j++)
            if (j < nj)
                CP_ASYNC16(hd + soff[j], (const char*)(xb + qoff[j] + c0));
        // B: all 9 taps at this c-chunk: 576 rows x 64 halves = 4608 chunks
        const uint32_t bd = sb + OFF_B + buf * BBUF;
        const __half* wsrc = g_wh + c0;
        #pragma unroll
        for (int j = 0; j < 18; j++) {
            const int i = tid + j * 256;
            const int row = i >> 3, seg = i & 7;
            CP_ASYNC16(bd + (uint32_t)(row * HS + seg * 8) * 2,
                       (const char*)(wsrc + (size_t)row * Cn + seg * 8));
        }
    };

    // ---- warp tiling: 4 (m) x 2 (n) warps; warp tile 32x32 ----
    const int wm = (wid & 3) * 32;
    const int wn = (wid >> 2) * 32;

    uint32_t abase[2];                    // per-lane A ldmatrix base (tap 0)
    #pragma unroll
    for (int mb = 0; mb < 2; mb++) {
        const int m   = wm + mb * 16 + (lid & 15);
        const int ent = (m >> 4) * 18 + (m & 15);
        abase[mb] = sb + OFF_H + (uint32_t)(ent * HS) * 2 + (uint32_t)(lid >> 4) * 16;
    }
    uint32_t bbase[2];                    // per-lane B ldmatrix base
    {
        const int br = (lid & 7) + ((lid >> 4) << 3);
        const uint32_t bcol = (uint32_t)(((lid >> 3) & 1) << 3) * 2;
        #pragma unroll
        for (int np = 0; np < 2; np++)
            bbase[np] = sb + OFF_B + (uint32_t)((wn + np * 16 + br) * HS) * 2 + bcol;
    }
    const int grow = (lid >> 2);          // gate row within warp m-block

    float facc[2][4][4];
    #pragma unroll
    for (int i = 0; i < 2; i++)
        #pragma unroll
        for (int j = 0; j < 4; j++)
            #pragma unroll
            for (int k = 0; k < 4; k++) facc[i][j][k] = 0.f;

    stage(0, 0); CP_COMMIT();
    stage(1, 1); CP_COMMIT();

    for (int e = 0; e < EPOCHS; e++) {
        const int buf = e & 1;

        if (e < EPOCHS - 1) { CP_WAIT1(); } else { CP_WAIT0(); }
        __syncthreads();    // staged data (and, first epoch, gates) visible

        const uint32_t habuf = (uint32_t)buf * HBUF;
        const uint32_t bbbuf = (uint32_t)buf * BBUF;

        #pragma unroll 3
        for (int t = 0; t < 9; t++) {
            const int trow = t / 3, tcol = t - trow * 3;
            const uint32_t aoff = habuf + (uint32_t)((trow * 18 + tcol) * (HS * 2));
            const uint32_t boff = bbbuf + (uint32_t)(t * On * (HS * 2));

            uint32_t g0[2], g1[2];        // (g,g) half2 per fragment row
            #pragma unroll
            for (int mb = 0; mb < 2; mb++) {
                const int r = wm + mb * 16 + grow;
                g0[mb] = g_sp[t * Mt + r];
                g1[mb] = g_sp[t * Mt + r + 8];
            }

            #pragma unroll
            for (int ks = 0; ks < 4; ks++) {
                uint32_t af[2][4];
                #pragma unroll
                for (int mb = 0; mb < 2; mb++) {
                    ldsm_x4(af[mb], abase[mb] + aoff + ks * 32);
                    af[mb][0] = hmul2u(af[mb][0], g0[mb]);
                    af[mb][1] = hmul2u(af[mb][1], g1[mb]);
                    af[mb][2] = hmul2u(af[mb][2], g0[mb]);
                    af[mb][3] = hmul2u(af[mb][3], g1[mb]);
                }
                uint32_t bf[2][4];
                #pragma unroll
                for (int np = 0; np < 2; np++)
                    ldsm_x4(bf[np], bbase[np] + boff + ks * 32);
                #pragma unroll
                for (int mb = 0; mb < 2; mb++)
                    #pragma unroll
                    for (int nb = 0; nb < 4; nb++)
                        mma16816(facc[mb][nb], af[mb],
                                 bf[nb >> 1][(nb & 1) * 2],
                                 bf[nb >> 1][(nb & 1) * 2 + 1]);
            }
        }

        if (e + 2 < EPOCHS) {
            __syncthreads();   // all warps done with this buffer
            stage(e + 2, buf);
            CP_COMMIT();
        }
    }

    // ---- epilogue: D(m=pixel, n=o) -> out[b][o][h][w] ----
    float* ob = out + (size_t)b * On * PIXn;
    const int mrow = wm + (lid >> 2);
    const int ncol = wn + (lid & 3) * 2;
    #pragma unroll
    for (int mb = 0; mb < 2; mb++) {
        #pragma unroll
        for (int half_ = 0; half_ < 2; half_++) {
            const int m  = mrow + mb * 16 + half_ * 8;
            const int hh = h0 + (m >> 4);
            const int ww = w0 + (m & 15);
            const int pix = hh * Wn + ww;
            #pragma unroll
            for (int nb = 0; nb < 4; nb++) {
                const int o = ncol + nb * 8;
                ob[(size_t)o * PIXn + pix]       = facc[mb][nb][half_ * 2];
                ob[(size_t)(o + 1) * PIXn + pix] = facc[mb][nb][half_ * 2 + 1];
            }
        }
    }
}

// ====================== launch ======================
extern "C" void kernel_launch(void* const* d_in, const int* in_sizes, int n_in,
                              void* d_out, int out_size) {
    const float* x     = (const float*)d_in[0];   // (8,512,64,64)
    const float* depth = (const float*)d_in[1];   // (8,1,64,64)
    const float* w     = (const float*)d_in[2];   // (64,512,3,3)
    float* out = (float*)d_out;                   // (8,64,64,64)

    cudaFuncSetAttribute(depthconv_mma,
                         cudaFuncAttributeMaxDynamicSharedMemorySize,
                         SMEM_TOTAL);

    prep_all<<<NT_BLK + NW_BLK, 256>>>(x, w);
    depthconv_mma<<<Bn * 32, 256, SMEM_TOTAL>>>(depth, out);
}

// round 7
// speedup vs baseline: 7.6769x; 1.0516x over previous
#include <cuda_runtime.h>
#include <cuda_fp16.h>
#include <cstdint>

// DepthConv: out[b,o,p] = sum_t gate[b,t,p] * sum_c w[t,o,c]*x[b,c,p+shift(t)]
// Epoch-major (c-chunk) loop: halo staged ONCE per epoch (double-buffered);
// within an epoch, 9 taps each restage a tiny 9KB B tile (triple-buffered).
// Gate applied to A fragments in fp16 (HMUL2). 84KB smem -> 2 CTAs/SM.

#define ALPHA_F 8.3f

constexpr int Bn = 8;
constexpr int Cn = 512;
constexpr int Hn = 64;
constexpr int Wn = 64;
constexpr int On = 64;
constexpr int PIXn = Hn * Wn;       // 4096

constexpr int Mt = 128;             // pixels per CTA (8 rows x 16 cols)
constexpr int KC = 64;              // c-chunk per epoch
constexpr int EPOCHS = Cn / KC;     // 8
constexpr int NIT = EPOCHS * 9;     // 72 (epoch-major, tap-minor)
constexpr int HE = 180;             // halo entries (10 x 18)
constexpr int HS = 72;              // smem row stride in halves (64 + 8 pad)

// ---- device-global scratch ----
__device__ __half g_xh[(size_t)Bn * PIXn * Cn];   // [b][pixel][c] fp16
__device__ __half g_wh[9 * On * Cn];              // [tap][o][c]  fp16

// ---- smem layout (bytes) ----
constexpr int HBUF = HE * HS * 2;            // 25920 (x2 buffers)
constexpr int BBUF = On * HS * 2;            // 9216  (x3 buffers)
constexpr int OFF_H = 0;
constexpr int OFF_B = 2 * HBUF;              // 51840
constexpr int OFF_G = OFF_B + 3 * BBUF;      // 79488 gates 9*128*4
constexpr int SMEM_TOTAL = OFF_G + 9 * Mt * 4;  // 84096 -> 2 CTAs/SM

// ====================== helpers ======================
__device__ __forceinline__ uint32_t smem_u32(const void* p) {
    uint32_t a;
    asm("{ .reg .u64 t; cvta.to.shared.u64 t, %1; cvt.u32.u64 %0, t; }"
        : "=r"(a) : "l"(p));
    return a;
}
__device__ __forceinline__ void ldsm_x4(uint32_t* r, uint32_t addr) {
    asm volatile("ldmatrix.sync.aligned.m8n8.x4.shared.b16 {%0,%1,%2,%3}, [%4];"
        : "=r"(r[0]), "=r"(r[1]), "=r"(r[2]), "=r"(r[3]) : "r"(addr));
}
__device__ __forceinline__ void mma16816(float* c, const uint32_t* a,
                                         uint32_t b0, uint32_t b1) {
    asm volatile(
        "mma.sync.aligned.m16n8k16.row.col.f32.f16.f16.f32 "
        "{%0,%1,%2,%3}, {%4,%5,%6,%7}, {%8,%9}, {%0,%1,%2,%3};"
        : "+f"(c[0]), "+f"(c[1]), "+f"(c[2]), "+f"(c[3])
        : "r"(a[0]), "r"(a[1]), "r"(a[2]), "r"(a[3]), "r"(b0), "r"(b1));
}
__device__ __forceinline__ uint32_t hmul2u(uint32_t a, uint32_t g) {
    __half2 r = __hmul2(*reinterpret_cast<__half2*>(&a),
                        *reinterpret_cast<__half2*>(&g));
    return *reinterpret_cast<uint32_t*>(&r);
}
#define CP_ASYNC16(dst, src) \
    asm volatile("cp.async.cg.shared.global [%0], [%1], 16;" \
                 :: "r"(dst), "l"(src) : "memory")
#define CP_COMMIT() asm volatile("cp.async.commit_group;" ::: "memory")
#define CP_WAIT1()  asm volatile("cp.async.wait_group 1;" ::: "memory")
#define CP_WAIT0()  asm volatile("cp.async.wait_group 0;" ::: "memory")

// ====================== fused pre-pass ======================
constexpr int NT_BLK = Bn * (Cn / 64) * (PIXn / 64);   // 4096
constexpr int NW_ELEM = 9 * On * Cn;                   // 294912
constexpr int NW_BLK = NW_ELEM / (256 * 8);            // 144

__global__ __launch_bounds__(256) void prep_all(const float* __restrict__ x,
                                                const float* __restrict__ w) {
    const int bi = blockIdx.x;
    if (bi < NT_BLK) {
        __shared__ float tile[64][65];
        const int b  = bi / ((Cn / 64) * (PIXn / 64));
        const int r  = bi % ((Cn / 64) * (PIXn / 64));
        const int c0 = (r / (PIXn / 64)) * 64;
        const int p0 = (r % (PIXn / 64)) * 64;
        const int lane = threadIdx.x & 31;
        const int wrp  = threadIdx.x >> 5;     // 0..7
        #pragma unroll
        for (int j = 0; j < 8; j++) {          // warp handles 8 c-rows
            const int c = wrp * 8 + j;
            const float2 v = *reinterpret_cast<const float2*>(
                &x[((size_t)(b * Cn + c0 + c)) * PIXn + p0 + lane * 2]);
            tile[c][lane * 2]     = v.x;
            tile[c][lane * 2 + 1] = v.y;
        }
        __syncthreads();
        #pragma unroll
        for (int j = 0; j < 8; j++) {          // warp handles 8 pixel-rows
            const int p = wrp * 8 + j;
            __half2 v = __floats2half2_rn(tile[lane * 2][p], tile[lane * 2 + 1][p]);
            *reinterpret_cast<__half2*>(
                &g_xh[((size_t)(b * PIXn + p0 + p)) * Cn + c0 + lane * 2]) = v;
        }
    } else {
        const int base = (bi - NT_BLK) * 2048 + threadIdx.x;
        #pragma unroll
        for (int j = 0; j < 8; j++) {
            const int idx = base + j * 256;          // [t][o][c]
            const int c = idx % Cn;
            const int o = (idx / Cn) % On;
            const int t = idx / (Cn * On);
            g_wh[idx] = __float2half_rn(w[((size_t)o * Cn + c) * 9 + t]);
        }
    }
}

// ====================== main kernel ======================
__global__ __launch_bounds__(256, 2) void depthconv_mma(
    const float* __restrict__ depth,
    float* __restrict__ out)
{
    extern __shared__ __align__(16) char smem[];
    const uint32_t sb = smem_u32(smem);
    uint32_t* g_sp = reinterpret_cast<uint32_t*>(smem + OFF_G);  // [9][128] half2

    const int tid = threadIdx.x;
    const int wid = tid >> 5;
    const int lid = tid & 31;

    const int blk = blockIdx.x;          // 0..255
    const int b   = blk >> 5;
    const int tl  = blk & 31;
    const int h0  = (tl >> 2) * 8;       // 8 pixel rows
    const int w0  = (tl & 3) * 16;       // 16 pixel cols

    // ---- gates: 9 taps x 128 pixels, stored as (g,g) half2 ----
    if (tid < Mt) {
        const int hh = h0 + (tid >> 4);
        const int ww = w0 + (tid & 15);
        const float* dptr = depth + b * PIXn;
        const float d0 = dptr[hh * Wn + ww];
        #pragma unroll
        for (int t = 0; t < 9; t++) {
            const int h2 = hh + t / 3 - 1, w2 = ww + t % 3 - 1;
            float g = 0.f;
            if (h2 >= 0 && h2 < Hn && w2 >= 0 && w2 < Wn)
                g = __expf(-ALPHA_F * fabsf(d0 - dptr[h2 * Wn + w2]));
            const __half gh = __float2half_rn(g);
            __half2 gp = __halves2half2(gh, gh);
            g_sp[t * Mt + tid] = *reinterpret_cast<uint32_t*>(&gp);
        }
    }

    // ---- halo staging slots (epoch-invariant addressing) ----
    const __half* xb = g_xh + (size_t)b * PIXn * Cn;
    const int nj = (tid < 160) ? 6 : 5;   // 1440 chunks over 256 threads
    int qoff[6];        // global half offset (add c0)
    uint32_t soff[6];   // smem byte offset within halo buffer
    #pragma unroll
    for (int j = 0; j < 6; j++) {
        const int i = tid + j * 256;
        const int ent = i >> 3, seg = i & 7;
        const int hr = ent / 18, hc = ent - hr * 18;
        const int hh = min(max(h0 - 1 + hr, 0), Hn - 1);
        const int ww = min(max(w0 - 1 + hc, 0), Wn - 1);
        qoff[j] = (hh * Wn + ww) * Cn + seg * 8;
        soff[j] = (uint32_t)(ent * HS + seg * 8) * 2;
    }
    // B staging: 64 rows x 8 segs = 512 chunks -> 2 per thread
    uint32_t bsoff[2];
    int boff[2];
    #pragma unroll
    for (int j = 0; j < 2; j++) {
        const int i = tid + j * 256;
        const int o = i >> 3, seg = i & 7;
        boff[j]  = o * Cn + seg * 8;              // add t*On*Cn + c0
        bsoff[j] = (uint32_t)(o * HS + seg * 8) * 2;
    }

    auto stage_halo = [&](int e, int buf) {
        const int c0 = e * KC;
        const uint32_t hd = sb + OFF_H + buf * HBUF;
        #pragma unroll
        for (int j = 0; j < 6; j++)
            if (j < nj)
                CP_ASYNC16(hd + soff[j], (const char*)(xb + qoff[j] + c0));
    };
    auto stage_B = [&](int it, int buf) {
        const int e = it / 9, t = it - e * 9;
        const uint32_t bd = sb + OFF_B + buf * BBUF;
        const __half* wsrc = g_wh + (size_t)t * On * Cn + e * KC;
        #pragma unroll
        for (int j = 0; j < 2; j++)
            CP_ASYNC16(bd + bsoff[j], (const char*)(wsrc + boff[j]));
    };

    // ---- warp tiling: 4 (m) x 2 (n) warps; warp tile 32x32 ----
    const int wm = (wid & 3) * 32;
    const int wn = (wid >> 2) * 32;

    uint32_t abase[2];                    // per-lane A ldmatrix base (tap 0)
    #pragma unroll
    for (int mb = 0; mb < 2; mb++) {
        const int m   = wm + mb * 16 + (lid & 15);
        const int ent = (m >> 4) * 18 + (m & 15);
        abase[mb] = sb + OFF_H + (uint32_t)(ent * HS) * 2 + (uint32_t)(lid >> 4) * 16;
    }
    uint32_t bbase[2];                    // per-lane B ldmatrix base
    {
        const int br = (lid & 7) + ((lid >> 4) << 3);
        const uint32_t bcol = (uint32_t)(((lid >> 3) & 1) << 3) * 2;
        #pragma unroll
        for (int np = 0; np < 2; np++)
            bbase[np] = sb + OFF_B + (uint32_t)((wn + np * 16 + br) * HS) * 2 + bcol;
    }
    const int grow = (lid >> 2);          // gate row within warp m-block

    float facc[2][4][4];
    #pragma unroll
    for (int i = 0; i < 2; i++)
        #pragma unroll
        for (int j = 0; j < 4; j++)
            #pragma unroll
            for (int k = 0; k < 4; k++) facc[i][j][k] = 0.f;

    stage_halo(0, 0); stage_B(0, 0); CP_COMMIT();   // group: halo(0)+B(0)
    stage_B(1, 1); CP_COMMIT();                     // group: B(1)

    for (int it = 0; it < NIT; it++) {
        const int e = it / 9, t = it - e * 9;

        if (it >= NIT - 2) { CP_WAIT0(); } else { CP_WAIT1(); }
        __syncthreads();    // staged data (and, first iter, gates) visible

        const int trow = t / 3, tcol = t - trow * 3;
        const uint32_t aoff = (uint32_t)(e & 1) * HBUF
                            + (uint32_t)((trow * 18 + tcol) * (HS * 2));
        const uint32_t boffb = (uint32_t)(it % 3) * BBUF;

        uint32_t g0[2], g1[2];            // (g,g) half2 per fragment row
        #pragma unroll
        for (int mb = 0; mb < 2; mb++) {
            const int r = wm + mb * 16 + grow;
            g0[mb] = g_sp[t * Mt + r];
            g1[mb] = g_sp[t * Mt + r + 8];
        }

        #pragma unroll
        for (int ks = 0; ks < 4; ks++) {
            uint32_t af[2][4];
            #pragma unroll
            for (int mb = 0; mb < 2; mb++) {
                ldsm_x4(af[mb], abase[mb] + aoff + ks * 32);
                af[mb][0] = hmul2u(af[mb][0], g0[mb]);
                af[mb][1] = hmul2u(af[mb][1], g1[mb]);
                af[mb][2] = hmul2u(af[mb][2], g0[mb]);
                af[mb][3] = hmul2u(af[mb][3], g1[mb]);
            }
            uint32_t bf[2][4];
            #pragma unroll
            for (int np = 0; np < 2; np++)
                ldsm_x4(bf[np], bbase[np] + boffb + ks * 32);
            #pragma unroll
            for (int mb = 0; mb < 2; mb++)
                #pragma unroll
                for (int nb = 0; nb < 4; nb++)
                    mma16816(facc[mb][nb], af[mb],
                             bf[nb >> 1][(nb & 1) * 2],
                             bf[nb >> 1][(nb & 1) * 2 + 1]);
        }

        // ---- post-compute staging (past barrier => prior readers done) ----
        if (it + 2 < NIT) {
            stage_B(it + 2, (it + 2) % 3);
            if (t == 0 && e + 1 < EPOCHS)
                stage_halo(e + 1, (e + 1) & 1);
            CP_COMMIT();
        }
    }

    // ---- epilogue: D(m=pixel, n=o) -> out[b][o][h][w] ----
    float* ob = out + (size_t)b * On * PIXn;
    const int mrow = wm + (lid >> 2);
    const int ncol = wn + (lid & 3) * 2;
    #pragma unroll
    for (int mb = 0; mb < 2; mb++) {
        #pragma unroll
        for (int half_ = 0; half_ < 2; half_++) {
            const int m  = mrow + mb * 16 + half_ * 8;
            const int hh = h0 + (m >> 4);
            const int ww = w0 + (m & 15);
            const int pix = hh * Wn + ww;
            #pragma unroll
            for (int nb = 0; nb < 4; nb++) {
                const int o = ncol + nb * 8;
                ob[(size_t)o * PIXn + pix]       = facc[mb][nb][half_ * 2];
                ob[(size_t)(o + 1) * PIXn + pix] = facc[mb][nb][half_ * 2 + 1];
            }
        }
    }
}

// ====================== launch ======================
extern "C" void kernel_launch(void* const* d_in, const int* in_sizes, int n_in,
                              void* d_out, int out_size) {
    const float* x     = (const float*)d_in[0];   // (8,512,64,64)
    const float* depth = (const float*)d_in[1];   // (8,1,64,64)
    const float* w     = (const float*)d_in[2];   // (64,512,3,3)
    float* out = (float*)d_out;                   // (8,64,64,64)

    cudaFuncSetAttribute(depthconv_mma,
                         cudaFuncAttributeMaxDynamicSharedMemorySize,
                         SMEM_TOTAL);

    prep_all<<<NT_BLK + NW_BLK, 256>>>(x, w);
    depthconv_mma<<<Bn * 32, 256, SMEM_TOTAL>>>(depth, out);
}